// round 14
// baseline (speedup 1.0000x reference)
#include <cuda_runtime.h>
#include <cuda_bf16.h>
#include <math.h>

// Problem shape (fixed by reference setup_inputs)
#define NN   32
#define CC   256
#define HH   56
#define WW   56
#define HWp  (HH * WW)        // 3136
#define NHWc (NN * HWp)       // 100352
#define KK   3
#define NW   (CC * CC * KK * KK)  // 589824
#define NBASE (NN * 7)        // k_base grid (224)

// ---------------------------------------------------------------------------
// Scratch (device globals only — no allocation allowed).
// Everything is fully overwritten each call -> no init kernel, graph-replay
// deterministic.
// ---------------------------------------------------------------------------
__device__ int       g_s[NHWc];          // per-pixel channel-sum of sign(x)
__device__ short     g_base[NHWc];       // 3x3 boxsum of g_s (|v| <= 2304, fits i16)
__device__ long long g_part1[NBASE];     // per-block boxsum partial sums
__device__ long long g_part2[NBASE];     // per-block boxsum partial sumsq
__device__ int       g_corr_cnt[CC];            // # of non-(+1) weight entries per out-channel
__device__ int       g_corr_ent[CC * CC * 9];   // packed (ci<<8 | kh<<4 | kw<<2 | cmag), cmag in {1,2}
__device__ float     g_scale[CC];
__device__ float     g_shift[CC];

// ---------------------------------------------------------------------------
// K1: weight scan — one WARP per output channel, ballot compaction, no
//     atomics, cnt overwritten every call (reset-free).
//       w > 0  -> wb=+1 -> skip
//       w == 0 -> wb= 0 -> cmag=1
//       w < 0  -> wb=-1 -> cmag=2
// ---------------------------------------------------------------------------
__global__ void k_wscan(const float* __restrict__ w) {
    int warp = (blockIdx.x * blockDim.x + threadIdx.x) >> 5;   // channel 0..255
    int lane = threadIdx.x & 31;
    const float* wc = w + (size_t)warp * (CC * 9);
    int* ents = g_corr_ent + warp * (CC * 9);

    int cnt = 0;
    for (int i = lane; i < CC * 9; i += 32) {
        float wv = wc[i];
        bool bad = !(wv > 0.f);
        unsigned m = __ballot_sync(0xffffffffu, bad);
        if (bad) {
            int pos = cnt + __popc(m & ((1u << lane) - 1));
            int ci = i / 9;
            int t  = i - ci * 9;
            int kh = t / 3, kw = t - kh * 3;
            int cmag = (wv < 0.f) ? 2 : 1;
            ents[pos] = (ci << 8) | (kh << 4) | (kw << 2) | cmag;
        }
        cnt += __popc(m);
    }
    if (lane == 0) g_corr_cnt[warp] = cnt;
}

// ---------------------------------------------------------------------------
// K2: s[n,h,w] = sum_ci sign(x[n,ci,h,w])   (reads all of x once, coalesced,
//     default cache policy: x fits in L2 (103MB < 126MB) and stays resident
//     for k_final).
// ---------------------------------------------------------------------------
__global__ void k_colsum(const float* __restrict__ x) {
    int idx = blockIdx.x * blockDim.x + threadIdx.x;   // over NHWc
    int n  = idx / HWp;
    int hw = idx - n * HWp;
    const float* p = x + (size_t)n * CC * HWp + hw;
    int acc = 0;
    #pragma unroll 32
    for (int ci = 0; ci < CC; ci++) {
        float v = p[(size_t)ci * HWp];
        acc += (v > 0.f) - (v < 0.f);
    }
    g_s[idx] = acc;
}

// ---------------------------------------------------------------------------
// K3: base = 3x3 zero-padded boxsum of s, smem-tiled; per-block partial
//     sum/sumsq written to g_part (no atomics, reset-free).
// ---------------------------------------------------------------------------
__global__ void k_base() {
    int blk = blockIdx.x;              // 0..223
    int n   = blk / 7;
    int r0  = (blk - n * 7) * 8;       // first output row of this strip

    __shared__ int s_s[10 * WW];       // rows r0-1 .. r0+8 (zero-padded)
    const int* sp = g_s + n * HWp;
    #pragma unroll
    for (int i = threadIdx.x; i < 10 * WW; i += 448) {
        int rr = r0 - 1 + i / WW;
        int cc = i - (i / WW) * WW;
        s_s[i] = ((unsigned)rr < HH) ? sp[rr * WW + cc] : 0;
    }
    __syncthreads();

    int lr = threadIdx.x / WW;         // 0..7 local row
    int w0 = threadIdx.x - lr * WW;    // 0..55
    int h  = r0 + lr;

    int acc = 0;
    #pragma unroll
    for (int kh = 0; kh < 3; kh++) {
        const int* row = s_s + (lr + kh) * WW;
        acc += row[w0];
        if (w0 > 0)      acc += row[w0 - 1];
        if (w0 < WW - 1) acc += row[w0 + 1];
    }
    g_base[n * HWp + h * WW + w0] = (short)acc;

    // int32 warp reduction (per-warp s2 <= 32*2304^2 = 1.7e8 < 2^31)
    int s1 = acc;
    int s2 = acc * acc;
    #pragma unroll
    for (int o = 16; o; o >>= 1) {
        s1 += __shfl_down_sync(0xffffffffu, s1, o);
        s2 += __shfl_down_sync(0xffffffffu, s2, o);
    }
    __shared__ int sh1[14], sh2[14];
    int lane = threadIdx.x & 31, wid = threadIdx.x >> 5;
    if (lane == 0) { sh1[wid] = s1; sh2[wid] = s2; }
    __syncthreads();
    if (threadIdx.x == 0) {
        long long t1 = 0, t2 = 0;
        #pragma unroll
        for (int i = 0; i < 14; i++) { t1 += sh1[i]; t2 += sh2[i]; }
        g_part1[blk] = t1;
        g_part2[blk] = t2;
    }
}

// ---------------------------------------------------------------------------
// K4: per-channel BN stats -> scale/shift.
//     cnt==0 channels: reduce the 224 k_base partials (L2-hot, trivial).
//     Corrected channels recompute y exactly (fallback; expected unused).
// ---------------------------------------------------------------------------
__global__ void k_stats(const float* __restrict__ x,
                        const float* __restrict__ gamma,
                        const float* __restrict__ beta) {
    int c = blockIdx.x;
    int cnt = g_corr_cnt[c];

    __shared__ long long sh1[8], sh2[8];
    int lane = threadIdx.x & 31, wid = threadIdx.x >> 5;

    long long s1 = 0, s2 = 0;

    if (cnt == 0) {
        if (threadIdx.x < NBASE) { s1 = g_part1[threadIdx.x]; s2 = g_part2[threadIdx.x]; }
    } else {
        const int* ents = g_corr_ent + c * (CC * 9);
        for (int e = threadIdx.x; e < NHWc; e += blockDim.x) {
            int n  = e / HWp;
            int hw = e - n * HWp;
            int h  = hw / WW, w0 = hw - h * WW;
            int y = g_base[e];
            for (int j = 0; j < cnt; j++) {
                int ent = ents[j];
                int ci = ent >> 8, kh = (ent >> 4) & 3, kw = (ent >> 2) & 3, cm = ent & 3;
                int hh = h + kh - 1, ww = w0 + kw - 1;
                if ((unsigned)hh < HH && (unsigned)ww < WW) {
                    float xv = x[((size_t)n * CC + ci) * HWp + hh * WW + ww];
                    int sg = (xv > 0.f) - (xv < 0.f);
                    y -= cm * sg;
                }
            }
            s1 += y;
            s2 += (long long)y * (long long)y;
        }
    }

    #pragma unroll
    for (int o = 16; o; o >>= 1) {
        s1 += __shfl_down_sync(0xffffffffu, s1, o);
        s2 += __shfl_down_sync(0xffffffffu, s2, o);
    }
    if (lane == 0) { sh1[wid] = s1; sh2[wid] = s2; }
    __syncthreads();
    if (threadIdx.x == 0) {
        long long t1 = 0, t2 = 0;
        #pragma unroll
        for (int i = 0; i < 8; i++) { t1 += sh1[i]; t2 += sh2[i]; }
        double mean = (double)t1 / (double)NHWc;
        double var  = (double)t2 / (double)NHWc - mean * mean;
        double rstd = 1.0 / sqrt(var + 1e-5);
        float sc = gamma[c] * (float)rstd;
        g_scale[c] = sc;
        g_shift[c] = beta[c] - sc * (float)mean;
    }
}

// ---------------------------------------------------------------------------
// K5: out = scale[c]*y + shift[c] + x.
//     One block per (n,c) plane, 256 threads (8 full warps).  All 3 chunk
//     load-pairs are issued up front (6 independent loads in flight per
//     thread), then compute+__stcs stores.  16-thread tail chunk after.
// ---------------------------------------------------------------------------
__device__ __forceinline__ void final_corr(
    int p, int n, int cnt, const int* __restrict__ ents,
    const float* __restrict__ x,
    int& y0, int& y1, int& y2, int& y3)
{
    int h = p / WW, w0 = p - h * WW;
    for (int j = 0; j < cnt; j++) {
        int ent = ents[j];
        int ci = ent >> 8, kh = (ent >> 4) & 3, kw = (ent >> 2) & 3, cm = ent & 3;
        int hh = h + kh - 1;
        if ((unsigned)hh >= HH) continue;
        const float* xr = x + ((size_t)n * CC + ci) * HWp + hh * WW;
        #pragma unroll
        for (int jj = 0; jj < 4; jj++) {
            int ww = w0 + jj + kw - 1;
            if ((unsigned)ww < WW) {
                float v = xr[ww];
                int d = cm * ((v > 0.f) - (v < 0.f));
                if      (jj == 0) y0 -= d;
                else if (jj == 1) y1 -= d;
                else if (jj == 2) y2 -= d;
                else              y3 -= d;
            }
        }
    }
}

__global__ void k_final(const float* __restrict__ x, float* __restrict__ out) {
    int b = blockIdx.x;
    int n = b >> 8, c = b & 255;
    float sc = g_scale[c], sh = g_shift[c];
    int cnt = g_corr_cnt[c];
    const int* ents = g_corr_ent + c * (CC * 9);
    size_t plane = ((size_t)n * CC + c) * HWp;
    const short* basep = g_base + n * HWp;
    int t = threadIdx.x;

    // Front-batch all main-chunk loads (6 independent LDGs in flight).
    float4 xv[3];
    short4 bi[3];
    #pragma unroll
    for (int k = 0; k < 3; k++) {
        int p = (t + k * 256) * 4;
        xv[k] = *(const float4*)(x + plane + p);
        bi[k] = *(const short4*)(basep + p);
    }

    #pragma unroll
    for (int k = 0; k < 3; k++) {
        int p = (t + k * 256) * 4;
        int y0 = bi[k].x, y1 = bi[k].y, y2 = bi[k].z, y3 = bi[k].w;
        if (cnt) final_corr(p, n, cnt, ents, x, y0, y1, y2, y3);
        float4 o;
        o.x = fmaf(sc, (float)y0, sh) + xv[k].x;
        o.y = fmaf(sc, (float)y1, sh) + xv[k].y;
        o.z = fmaf(sc, (float)y2, sh) + xv[k].z;
        o.w = fmaf(sc, (float)y3, sh) + xv[k].w;
        __stcs((float4*)(out + plane + p), o);
    }

    if (t < 16) {
        int p = (t + 768) * 4;
        float4 xt = *(const float4*)(x + plane + p);
        short4 bt = *(const short4*)(basep + p);
        int y0 = bt.x, y1 = bt.y, y2 = bt.z, y3 = bt.w;
        if (cnt) final_corr(p, n, cnt, ents, x, y0, y1, y2, y3);
        float4 o;
        o.x = fmaf(sc, (float)y0, sh) + xt.x;
        o.y = fmaf(sc, (float)y1, sh) + xt.y;
        o.z = fmaf(sc, (float)y2, sh) + xt.z;
        o.w = fmaf(sc, (float)y3, sh) + xt.w;
        __stcs((float4*)(out + plane + p), o);
    }
}

// ---------------------------------------------------------------------------
// kernel_launch — inputs: x, w, gamma, beta ; output: float32 [32,256,56,56]
// 5 launches (k_init eliminated; all scratch is overwrite-only).
// ---------------------------------------------------------------------------
extern "C" void kernel_launch(void* const* d_in, const int* in_sizes, int n_in,
                              void* d_out, int out_size) {
    const float* x     = (const float*)d_in[0];
    const float* w     = (const float*)d_in[1];
    const float* gamma = (const float*)d_in[2];
    const float* beta  = (const float*)d_in[3];
    float* out = (float*)d_out;

    k_wscan <<<CC / 8, 256>>>(w);        // 256 warps, one per channel
    k_colsum<<<NHWc / 256, 256>>>(x);
    k_base  <<<NBASE, 448>>>();
    k_stats <<<CC, 256>>>(x, gamma, beta);
    k_final <<<NN * CC, 256>>>(x, out);
}